// round 12
// baseline (speedup 1.0000x reference)
#include <cuda_runtime.h>
#include <math.h>

// Problem constants (fixed shapes from reference: T=16384, H=4096, E=64, TOPK=8)
#define KH      4096          // hidden dim (K of the GEMM)
#define NEXP    64            // experts (N of the GEMM)
#define TOPK    8
#define TM      128           // rows per CTA
#define KC      32            // K tile
#define NT      (KH / KC)     // 128 K tiles
#define A_STRIDE 132          // padded smem stride for transposed A (mult of 4 for 16B LDS)
#define B_STRIDE 64           // B row stride: MUST be >= NEXP (Round 10 bug: 60 overflowed smem)
#define P_STRIDE 68           // padded stride for probs tile (mult of 4)

// smem float counts
#define AS_FLOATS (2 * KC * A_STRIDE)      // 8448  (33792 B)
#define BS_FLOATS (2 * KC * B_STRIDE)      // 4096  (16384 B)
#define SMEM_BYTES ((AS_FLOATS + BS_FLOATS) * 4)   // 50176 B (needs opt-in > 48KB)
// epilogue probs tile: 128*68*4 = 34816 B, aliases the GEMM tiles

typedef unsigned long long u64;

__device__ __forceinline__ u64 fma2(u64 a, u64 b, u64 c) {
    u64 d;
    asm("fma.rn.f32x2 %0, %1, %2, %3;" : "=l"(d) : "l"(a), "l"(b), "l"(c));
    return d;
}

__device__ __forceinline__ u64 dup2(float x) {
    u64 r;
    asm("mov.b64 %0, {%1, %1};" : "=l"(r) : "f"(x));
    return r;
}

extern __shared__ float smem[];

__global__ void __launch_bounds__(256, 1)
moe_router_kernel(const float* __restrict__ X,     // [T, H]
                  const float* __restrict__ W,     // [E, H]
                  const float* __restrict__ Bias,  // [E]
                  float* __restrict__ w_out,       // [T,8]  or null
                  float* __restrict__ idx_out,     // [T,8]  or null
                  float* __restrict__ probs_out,   // [T,64] or null
                  int T)
{
    const int tid = threadIdx.x;
    const int tx  = tid & 15;        // expert group: experts tx*4 .. tx*4+3
    const int ty  = tid >> 4;        // row group:    rows ty*8 .. ty*8+7
    const int row0 = blockIdx.x * TM;

    float* As = smem;                         // [2][KC][A_STRIDE] transposed: As[k][m]
    float* Bs = smem + AS_FLOATS;             // [2][KC][B_STRIDE] transposed: Bs[k][e]

    // global-load index mapping
    const int a_row = tid >> 3;               // 0..31 (4 passes -> 128 rows)
    const int a_k4  = tid & 7;                // float4 index within KC
    const int b_e   = tid & 31;               // 0..31 (2 passes -> 64 experts)
    const int b_k4  = tid >> 5;               // 0..7

    const float4* Xv = reinterpret_cast<const float4*>(X);
    const float4* Wv = reinterpret_cast<const float4*>(W);
    const int HV = KH / 4;                    // 1024 float4s per row

    float4 areg[4], breg[2];

    auto ldg_tile = [&](int kt) {
        const int kb = kt * 8;                // float4 offset in K
        #pragma unroll
        for (int p = 0; p < 4; p++)
            areg[p] = Xv[(size_t)(row0 + a_row + p * 32) * HV + kb + a_k4];
        #pragma unroll
        for (int p = 0; p < 2; p++)
            breg[p] = Wv[(size_t)(b_e + p * 32) * HV + kb + b_k4];
    };

    auto sts_tile = [&](int buf) {
        float* A  = As + buf * KC * A_STRIDE;
        float* Bt = Bs + buf * KC * B_STRIDE;
        #pragma unroll
        for (int p = 0; p < 4; p++) {
            const int r = a_row + p * 32;
            A[(a_k4 * 4 + 0) * A_STRIDE + r] = areg[p].x;
            A[(a_k4 * 4 + 1) * A_STRIDE + r] = areg[p].y;
            A[(a_k4 * 4 + 2) * A_STRIDE + r] = areg[p].z;
            A[(a_k4 * 4 + 3) * A_STRIDE + r] = areg[p].w;
        }
        #pragma unroll
        for (int p = 0; p < 2; p++) {
            const int e = b_e + p * 32;
            Bt[(b_k4 * 4 + 0) * B_STRIDE + e] = breg[p].x;
            Bt[(b_k4 * 4 + 1) * B_STRIDE + e] = breg[p].y;
            Bt[(b_k4 * 4 + 2) * B_STRIDE + e] = breg[p].z;
            Bt[(b_k4 * 4 + 3) * B_STRIDE + e] = breg[p].w;
        }
    };

    // accumulators: 4 row-pairs x 4 experts, packed f32x2 (lo = even row of pair)
    u64 acc[4][4];
    #pragma unroll
    for (int i = 0; i < 4; i++)
        #pragma unroll
        for (int j = 0; j < 4; j++)
            acc[i][j] = 0ULL;

    ldg_tile(0);
    sts_tile(0);
    __syncthreads();

    for (int kt = 0; kt < NT; kt++) {
        const int cur = kt & 1;
        if (kt + 1 < NT) ldg_tile(kt + 1);

        const float* A  = As + cur * KC * A_STRIDE;
        const float* Bt = Bs + cur * KC * B_STRIDE;

        #pragma unroll
        for (int k = 0; k < KC; k++) {
            // 8 row values for this thread, as 4 packed pairs (16B-aligned: A_STRIDE%4==0)
            ulonglong2 A01 = *reinterpret_cast<const ulonglong2*>(A + k * A_STRIDE + ty * 8);
            ulonglong2 A23 = *reinterpret_cast<const ulonglong2*>(A + k * A_STRIDE + ty * 8 + 4);
            float4 b = *reinterpret_cast<const float4*>(Bt + k * B_STRIDE + tx * 4);

            u64 ap0 = A01.x, ap1 = A01.y, ap2 = A23.x, ap3 = A23.y;

            u64 bb0 = dup2(b.x), bb1 = dup2(b.y), bb2 = dup2(b.z), bb3 = dup2(b.w);

            acc[0][0] = fma2(ap0, bb0, acc[0][0]);
            acc[1][0] = fma2(ap1, bb0, acc[1][0]);
            acc[2][0] = fma2(ap2, bb0, acc[2][0]);
            acc[3][0] = fma2(ap3, bb0, acc[3][0]);
            acc[0][1] = fma2(ap0, bb1, acc[0][1]);
            acc[1][1] = fma2(ap1, bb1, acc[1][1]);
            acc[2][1] = fma2(ap2, bb1, acc[2][1]);
            acc[3][1] = fma2(ap3, bb1, acc[3][1]);
            acc[0][2] = fma2(ap0, bb2, acc[0][2]);
            acc[1][2] = fma2(ap1, bb2, acc[1][2]);
            acc[2][2] = fma2(ap2, bb2, acc[2][2]);
            acc[3][2] = fma2(ap3, bb2, acc[3][2]);
            acc[0][3] = fma2(ap0, bb3, acc[0][3]);
            acc[1][3] = fma2(ap1, bb3, acc[1][3]);
            acc[2][3] = fma2(ap2, bb3, acc[2][3]);
            acc[3][3] = fma2(ap3, bb3, acc[3][3]);
        }

        __syncthreads();                       // all threads done reading cur (and prior buf)
        if (kt + 1 < NT) {
            sts_tile((kt + 1) & 1);
            __syncthreads();
        }
    }

    // ---- epilogue: bias + sigmoid -> probs (gmem + smem), then per-row top-8 ----
    __syncthreads();                           // safe to alias smem now

    float4 bias4 = reinterpret_cast<const float4*>(Bias)[tx];
    float bb[4] = {bias4.x, bias4.y, bias4.z, bias4.w};

    float* probs_s = smem;                     // [TM][P_STRIDE], 34816B <= 50176B

    #pragma unroll
    for (int i = 0; i < 4; i++) {
        #pragma unroll
        for (int h2 = 0; h2 < 2; h2++) {
            const int m = ty * 8 + i * 2 + h2;
            float p[4];
            #pragma unroll
            for (int j = 0; j < 4; j++) {
                unsigned u = h2 ? (unsigned)(acc[i][j] >> 32)
                               : (unsigned)(acc[i][j] & 0xffffffffULL);
                float lg = __uint_as_float(u) + bb[j];
                p[j] = 1.0f / (1.0f + expf(-lg));
            }
            float4 pv = make_float4(p[0], p[1], p[2], p[3]);
            *reinterpret_cast<float4*>(probs_s + m * P_STRIDE + tx * 4) = pv;
            if (probs_out)
                *reinterpret_cast<float4*>(probs_out + (size_t)(row0 + m) * NEXP + tx * 4) = pv;
        }
    }
    __syncthreads();

    if (tid < TM) {
        const int m = tid;
        const float* pr = probs_s + m * P_STRIDE;

        float v[TOPK];
        int   ix[TOPK];
        #pragma unroll
        for (int j = 0; j < TOPK; j++) { v[j] = -1e30f; ix[j] = 0; }

        for (int e = 0; e < NEXP; e++) {
            float p = pr[e];
            if (p > v[TOPK - 1]) {             // strict >: stable, lower index wins ties
                v[TOPK - 1] = p; ix[TOPK - 1] = e;
                #pragma unroll
                for (int j = TOPK - 1; j > 0; j--) {
                    if (v[j] > v[j - 1]) {     // strict >: preserve stable order on ties
                        float tv = v[j]; v[j] = v[j - 1]; v[j - 1] = tv;
                        int   ti = ix[j]; ix[j] = ix[j - 1]; ix[j - 1] = ti;
                    }
                }
            }
        }

        float s = 0.0f;
        #pragma unroll
        for (int j = 0; j < TOPK; j++) s += v[j];

        const size_t rg = (size_t)(row0 + m);
        if (w_out) {
            float4 w0 = make_float4(v[0] / s, v[1] / s, v[2] / s, v[3] / s);
            float4 w1 = make_float4(v[4] / s, v[5] / s, v[6] / s, v[7] / s);
            float* wp = w_out + rg * TOPK;
            reinterpret_cast<float4*>(wp)[0] = w0;
            reinterpret_cast<float4*>(wp)[1] = w1;
        }
        if (idx_out) {
            float4 i0 = make_float4((float)ix[0], (float)ix[1], (float)ix[2], (float)ix[3]);
            float4 i1 = make_float4((float)ix[4], (float)ix[5], (float)ix[6], (float)ix[7]);
            float* ip = idx_out + rg * TOPK;
            reinterpret_cast<float4*>(ip)[0] = i0;
            reinterpret_cast<float4*>(ip)[1] = i1;
        }
    }
}

extern "C" void kernel_launch(void* const* d_in, const int* in_sizes, int n_in,
                              void* d_out, int out_size)
{
    const float* X    = (const float*)d_in[0];   // hidden_states [T, H]
    const float* W    = (const float*)d_in[1];   // W [E, H]
    const float* Bias = (const float*)d_in[2];   // b [E]

    const int E = in_sizes[2];                   // 64
    const int H = in_sizes[1] / E;               // 4096
    const int T = in_sizes[0] / H;               // 16384

    float* out = (float*)d_out;

    // Derive output layout from out_size (elements). Reference returns
    // (routing_weights [T,8], routing_indices [T,8], router_probs [T,64]);
    // gate each segment so we never write past out_size.
    const long long n = (long long)out_size;
    float* w_out     = nullptr;
    float* idx_out   = nullptr;
    float* probs_out = nullptr;

    if (n >= (long long)T * 80) {                // w | idx | probs
        w_out     = out;
        idx_out   = out + (size_t)T * 8;
        probs_out = out + (size_t)T * 16;
    } else if (n >= (long long)T * 72) {         // w | probs
        w_out     = out;
        probs_out = out + (size_t)T * 8;
    } else if (n >= (long long)T * 64) {         // probs only
        probs_out = out;
    } else if (n >= (long long)T * 16) {         // w | idx
        w_out   = out;
        idx_out = out + (size_t)T * 8;
    } else {                                     // w only
        w_out = out;
    }

    cudaFuncSetAttribute(moe_router_kernel,
                         cudaFuncAttributeMaxDynamicSharedMemorySize, SMEM_BYTES);

    dim3 grid(T / TM);
    moe_router_kernel<<<grid, 256, SMEM_BYTES>>>(X, W, Bias,
                                                 w_out, idx_out, probs_out, T);
}